// round 11
// baseline (speedup 1.0000x reference)
#include <cuda_runtime.h>
#include <cuda_bf16.h>
#include <cuda_fp16.h>
#include <cstdint>

#define BATCH   4
#define TFRAMES 32
#define NPTS    4096
#define FOUT    16
#define GROUPS  64
#define MANCH   128
#define KNBR    32
#define C0      64
#define C1      128

__device__ float4 g_disp[3 * GROUPS * MANCH * KNBR];   // 12.58 MB scratch

typedef unsigned long long ull;

__device__ __forceinline__ ull fma2(ull a, ull b, ull c) {
    ull d;
    asm("fma.rn.f32x2 %0, %1, %2, %3;" : "=l"(d) : "l"(a), "l"(b), "l"(c));
    return d;
}
__device__ __forceinline__ ull packf(float lo, float hi) {
    ull r;
    asm("mov.b64 %0, {%1, %2};" : "=l"(r) : "f"(lo), "f"(hi));
    return r;
}
__device__ __forceinline__ void unpackf(ull v, float& lo, float& hi) {
    asm("mov.b64 {%0, %1}, %2;" : "=f"(lo), "=f"(hi) : "l"(v));
}

// ---------------------------------------------------------------------------
// Kernel 1: FPS. 128 threads (4 warps), 32 pts/thread in registers.
// (R9-proven version: packed fma distances, scalar min/max.)
// ---------------------------------------------------------------------------
__global__ __launch_bounds__(128) void fps_kernel(const float* __restrict__ xyzs,
                                                  float* __restrict__ out_xyz) {
    const int g = blockIdx.x;
    const int b = g >> 4, f = g & 15;
    const float* fr = xyzs + ((size_t)(b * TFRAMES + 2 * f) * NPTS) * 3;
    const int tid = threadIdx.x;
    const int wid = tid >> 5, lane = tid & 31;

    __shared__ float sp[NPTS * 3];                 // 48 KB
    __shared__ ull wkey[2][4];
    for (int i = tid; i < NPTS * 3; i += 128) sp[i] = fr[i];
    __syncthreads();

    const ull ONE2 = packf(1.0f, 1.0f);
    ull px2[16], py2[16], pz2[16];
    float dist[32];
#pragma unroll
    for (int j = 0; j < 16; ++j) {
        int p0 = j * 256 + tid, p1 = p0 + 128;
        px2[j] = packf(sp[p0 * 3 + 0], sp[p1 * 3 + 0]);
        py2[j] = packf(sp[p0 * 3 + 1], sp[p1 * 3 + 1]);
        pz2[j] = packf(sp[p0 * 3 + 2], sp[p1 * 3 + 2]);
        dist[2 * j] = 1e10f; dist[2 * j + 1] = 1e10f;
    }

    float cx = sp[0], cy = sp[1], cz = sp[2];
    if (tid == 0) {
        float* o = out_xyz + (size_t)g * MANCH * 3;
        o[0] = cx; o[1] = cy; o[2] = cz;
    }

    for (int s = 1; s < MANCH; ++s) {
        const ull ncx2 = packf(-cx, -cx);
        const ull ncy2 = packf(-cy, -cy);
        const ull ncz2 = packf(-cz, -cz);
#pragma unroll
        for (int j = 0; j < 16; ++j) {
            ull ax = fma2(px2[j], ONE2, ncx2);
            ull ay = fma2(py2[j], ONE2, ncy2);
            ull az = fma2(pz2[j], ONE2, ncz2);
            ull mx = fma2(ax, ax, 0ull);
            ull my = fma2(ay, ay, 0ull);
            ull s1 = fma2(mx, ONE2, my);
            ull mz = fma2(az, az, 0ull);
            ull d2 = fma2(s1, ONE2, mz);
            float dlo, dhi;
            unpackf(d2, dlo, dhi);
            dist[2 * j]     = fminf(dist[2 * j], dlo);
            dist[2 * j + 1] = fminf(dist[2 * j + 1], dhi);
        }
        float t[16];
#pragma unroll
        for (int i = 0; i < 16; ++i) t[i] = fmaxf(dist[2 * i], dist[2 * i + 1]);
#pragma unroll
        for (int st = 8; st; st >>= 1)
#pragma unroll
            for (int i = 0; i < 8; ++i)
                if (i < st) t[i] = fmaxf(t[i], t[i + st]);
        unsigned wmax = __reduce_max_sync(0xffffffffu, __float_as_uint(t[0]));
        float wvf = __uint_as_float(wmax);
        unsigned cand = 0xffffffffu;
#pragma unroll
        for (int sl = 0; sl < 32; ++sl) {
            unsigned gi = (sl >> 1) * 256 + (sl & 1) * 128 + tid;
            if (dist[sl] == wvf) cand = min(cand, gi);
        }
        cand = __reduce_min_sync(0xffffffffu, cand);
        if (lane == 0)
            wkey[s & 1][wid] = ((ull)wmax << 32) | (unsigned)(~cand);
        __syncthreads();
        const ull* kk = wkey[s & 1];
        ull best = max(max(kk[0], kk[1]), max(kk[2], kk[3]));
        int wi = (int)(~(unsigned)best);
        cx = sp[wi * 3 + 0]; cy = sp[wi * 3 + 1]; cz = sp[wi * 3 + 2];
        if (tid == 0) {
            float* o = out_xyz + ((size_t)g * MANCH + s) * 3;
            o[0] = cx; o[1] = cy; o[2] = cz;
        }
    }
}

// ---------------------------------------------------------------------------
// Kernel 2: ball query (unchanged; proven)
// ---------------------------------------------------------------------------
__global__ __launch_bounds__(256) void ball_kernel(const float* __restrict__ xyzs,
                                                   const float* __restrict__ anchors) {
    const int bid = blockIdx.x;
    const int g = bid / 3, dti = bid % 3;
    const int dt = dti - 1;
    const int b = g >> 4, f = g & 15;
    int t = 2 * f + dt;
    t = min(max(t, 0), TFRAMES - 1);
    const float* fr = xyzs + (size_t)(b * TFRAMES + t) * NPTS * 3;

    __shared__ float sx[NPTS], sy[NPTS], sz[NPTS];
    for (int p = threadIdx.x; p < NPTS; p += 256) {
        const float* pp = fr + p * 3;
        sx[p] = pp[0]; sy[p] = pp[1]; sz[p] = pp[2];
    }
    __syncthreads();

    const int w = threadIdx.x >> 5;
    const int lane = threadIdx.x & 31;
    const float r2 = (float)(0.15 * 0.15);
    const float tch = (float)dt;
    const ull ONE2 = packf(1.0f, 1.0f);
    const unsigned below = (1u << lane) - 1u;

    for (int m = w; m < MANCH; m += 8) {
        const float* a = anchors + ((size_t)g * MANCH + m) * 3;
        const float ax = a[0], ay = a[1], az = a[2];
        const ull nax2 = packf(-ax, -ax);
        const ull nay2 = packf(-ay, -ay);
        const ull naz2 = packf(-az, -az);
        float4* od = g_disp + ((size_t)(dti * GROUPS + g) * MANCH + m) * KNBR;

        int filled = 0;
        int firstidx = -1;

        for (int base = 0; base < NPTS; base += 128) {
            const int j0 = base + 4 * lane;
            float4 X = *(const float4*)(sx + j0);
            float4 Y = *(const float4*)(sy + j0);
            float4 Z = *(const float4*)(sz + j0);
            ull dxa = fma2(packf(X.x, X.y), ONE2, nax2);
            ull dxb = fma2(packf(X.z, X.w), ONE2, nax2);
            ull dya = fma2(packf(Y.x, Y.y), ONE2, nay2);
            ull dyb = fma2(packf(Y.z, Y.w), ONE2, nay2);
            ull dza = fma2(packf(Z.x, Z.y), ONE2, naz2);
            ull dzb = fma2(packf(Z.z, Z.w), ONE2, naz2);
            ull s1a = fma2(fma2(dxa, dxa, 0ull), ONE2, fma2(dya, dya, 0ull));
            ull s1b = fma2(fma2(dxb, dxb, 0ull), ONE2, fma2(dyb, dyb, 0ull));
            ull d2a = fma2(s1a, ONE2, fma2(dza, dza, 0ull));
            ull d2b = fma2(s1b, ONE2, fma2(dzb, dzb, 0ull));
            float d0, d1, d2, d3;
            unpackf(d2a, d0, d1);
            unpackf(d2b, d2, d3);
            bool p0 = d0 < r2, p1 = d1 < r2, p2 = d2 < r2, p3 = d3 < r2;
            unsigned m0 = __ballot_sync(0xffffffffu, p0);
            unsigned m1 = __ballot_sync(0xffffffffu, p1);
            unsigned m2 = __ballot_sync(0xffffffffu, p2);
            unsigned m3 = __ballot_sync(0xffffffffu, p3);
            unsigned anyh = m0 | m1 | m2 | m3;
            if (anyh) {
                int pos = filled + __popc(m0 & below) + __popc(m1 & below)
                                 + __popc(m2 & below) + __popc(m3 & below);
                float x0, x1, y0, y1, z0, z1, x2, x3, y2, y3, z2, z3;
                unpackf(dxa, x0, x1); unpackf(dya, y0, y1); unpackf(dza, z0, z1);
                unpackf(dxb, x2, x3); unpackf(dyb, y2, y3); unpackf(dzb, z2, z3);
                if (p0) { if (pos < KNBR) od[pos] = make_float4(x0, y0, z0, tch); pos++; }
                if (p1) { if (pos < KNBR) od[pos] = make_float4(x1, y1, z1, tch); pos++; }
                if (p2) { if (pos < KNBR) od[pos] = make_float4(x2, y2, z2, tch); pos++; }
                if (p3) { if (pos < KNBR) od[pos] = make_float4(x3, y3, z3, tch); pos++; }
                if (firstidx < 0) {
                    unsigned i0 = m0 ? 4u * (__ffs(m0) - 1)     : 0xffffu;
                    unsigned i1 = m1 ? 4u * (__ffs(m1) - 1) + 1 : 0xffffu;
                    unsigned i2 = m2 ? 4u * (__ffs(m2) - 1) + 2 : 0xffffu;
                    unsigned i3 = m3 ? 4u * (__ffs(m3) - 1) + 3 : 0xffffu;
                    firstidx = base + (int)min(min(i0, i1), min(i2, i3));
                }
                filled += __popc(m0) + __popc(m1) + __popc(m2) + __popc(m3);
                if (filled >= KNBR) break;
            }
        }
        if (filled < KNBR) {
            int fi = (firstidx < 0) ? 0 : firstidx;
            float fx = sx[fi] - ax, fy = sy[fi] - ay, fz = sz[fi] - az;
            int s = filled + lane;
            if (s < KNBR) od[s] = make_float4(fx, fy, fz, tch);
        }
    }
}

// ---------------------------------------------------------------------------
// Kernel 3: MLP. 256 threads (8 warps), warp owns 16 channels (mt=1).
// Phases: produce 3 dt-subtiles, 1 barrier, consume 3. 9 barriers total.
// ---------------------------------------------------------------------------
#define HBW 36
#define TILEW (64 * HBW)
#define TILEB (TILEW * 4)

#define MMA_F16(d, a, b0, b1)                                                   \
    asm("mma.sync.aligned.m16n8k16.row.col.f32.f16.f16.f32 "                    \
        "{%0,%1,%2,%3}, {%4,%5,%6,%7}, {%8,%9}, {%0,%1,%2,%3};"                 \
        : "+f"((d)[0]), "+f"((d)[1]), "+f"((d)[2]), "+f"((d)[3])                \
        : "r"((a)[0]), "r"((a)[1]), "r"((a)[2]), "r"((a)[3]), "r"(b0), "r"(b1))

#define LDM_X4(r0, r1, r2, r3, addr)                                            \
    asm volatile("ldmatrix.sync.aligned.m8n8.x4.shared.b16 {%0,%1,%2,%3}, [%4];" \
        : "=r"(r0), "=r"(r1), "=r"(r2), "=r"(r3) : "r"(addr))

__global__ __launch_bounds__(256, 1) void mlp_kernel(const float* __restrict__ Wd,
                                                     const float* __restrict__ Wm,
                                                     float* __restrict__ out) {
    extern __shared__ __align__(16) uint32_t s_hb[];        // [2][3][TILEW]
    __shared__ __align__(16) ull s_wdp[32][4];              // col-pair packed Wd
    __shared__ float s_obuf[C1 * 16];

    const int tid = threadIdx.x;
    const int w = tid >> 5, lane = tid & 31;
    const int q = lane & 3, nl = lane >> 2;
    const int g = blockIdx.x >> 3;
    const int m_base = (blockIdx.x & 7) * 16;

    if (tid < 128) {
        const int p = tid >> 2, c = tid & 3;
        s_wdp[p][c] = packf(Wd[(2 * p) * 4 + c], Wd[(2 * p + 1) * 4 + c]);
    }

    // A-fragments: warp w owns channels [16w, 16w+16). Exact fp16 hi+lo split.
    uint32_t Ah[4][4], Al[4][4];
#pragma unroll
    for (int rr = 0; rr < 2; ++rr) {
        const int r = 16 * w + 8 * rr + nl;
        const float* wr = Wm + (size_t)r * C0;
#pragma unroll
        for (int kt = 0; kt < 4; ++kt)
#pragma unroll
            for (int hf = 0; hf < 2; ++hf) {
                float2 v = *(const float2*)(wr + kt * 16 + 8 * hf + 2 * q);
                __half2 h2 = __floats2half2_rn(v.x, v.y);
                __half2 l2 = __floats2half2_rn(v.x - __low2float(h2),
                                               v.y - __high2float(h2));
                Ah[kt][rr + 2 * hf] = *(uint32_t*)&h2;
                Al[kt][rr + 2 * hf] = *(uint32_t*)&l2;
            }
    }
    __syncthreads();

    // producer mapping: thread -> (anchor, k, col-quarter)
    const int l1_a = tid >> 7;
    const int l1_k = (tid >> 2) & 31;
    const int l1_q = tid & 3;
    const int prow = l1_a * 32 + l1_k;
    const ull* wp = &s_wdp[l1_q * 8][0];

    const uint32_t hb0 = (uint32_t)__cvta_generic_to_shared(&s_hb[0]);
    const uint32_t laneoff = (uint32_t)((lane & 7) * (HBW * 4) + (lane >> 3) * 16);

    auto produce = [&](int pair, int buf) {
        const int m = m_base + pair * 2 + l1_a;
        float4 dv[3];
#pragma unroll
        for (int sub = 0; sub < 3; ++sub)
            dv[sub] = g_disp[((size_t)(sub * GROUPS + g) * MANCH + m) * KNBR + l1_k];
#pragma unroll
        for (int sub = 0; sub < 3; ++sub) {
            const ull dvx2 = packf(dv[sub].x, dv[sub].x);
            const ull dvy2 = packf(dv[sub].y, dv[sub].y);
            const ull dvz2 = packf(dv[sub].z, dv[sub].z);
            const ull dvw2 = packf(dv[sub].w, dv[sub].w);
            uint32_t* hrow = &s_hb[(buf * 3 + sub) * TILEW + prow * HBW + l1_q * 8];
#pragma unroll
            for (int j = 0; j < 8; ++j) {
                ull acc = fma2(wp[4 * j + 0], dvx2, 0ull);
                acc = fma2(wp[4 * j + 1], dvy2, acc);
                acc = fma2(wp[4 * j + 2], dvz2, acc);
                acc = fma2(wp[4 * j + 3], dvw2, acc);
                float h0, h1;
                unpackf(acc, h0, h1);
                __half2 p = __floats2half2_rn(fmaxf(h0, 0.f), fmaxf(h1, 0.f));
                hrow[j] = *(uint32_t*)&p;
            }
        }
    };

    float fsum[2][2];   // [rowhalf][anchor]
#pragma unroll
    for (int i = 0; i < 4; ++i) (&fsum[0][0])[i] = 0.f;

    produce(0, 0);
    __syncthreads();

    for (int pair = 0; pair < 8; ++pair) {
        const int buf = pair & 1;
#pragma unroll
        for (int sub = 0; sub < 3; ++sub) {
            float acc[8][4];
#pragma unroll
            for (int i = 0; i < 32; ++i) (&acc[0][0])[i] = 0.f;
            const uint32_t ab = hb0 + (uint32_t)(buf * 3 + sub) * TILEB + laneoff;
#pragma unroll
            for (int ntp = 0; ntp < 4; ++ntp) {
                const int nt0 = 2 * ntp, nt1 = nt0 + 1;
                uint32_t b0[8], b1[8];
                const uint32_t r0 = (uint32_t)(nt0 * 8 * HBW * 4);
                const uint32_t r1 = (uint32_t)(nt1 * 8 * HBW * 4);
                LDM_X4(b0[0], b0[1], b0[2], b0[3], ab + r0);
                LDM_X4(b0[4], b0[5], b0[6], b0[7], ab + r0 + 64);
                LDM_X4(b1[0], b1[1], b1[2], b1[3], ab + r1);
                LDM_X4(b1[4], b1[5], b1[6], b1[7], ab + r1 + 64);
#pragma unroll
                for (int kt = 0; kt < 4; ++kt) {
                    MMA_F16(acc[nt0], Ah[kt], b0[2 * kt], b0[2 * kt + 1]);
                    MMA_F16(acc[nt1], Ah[kt], b1[2 * kt], b1[2 * kt + 1]);
                    MMA_F16(acc[nt0], Al[kt], b0[2 * kt], b0[2 * kt + 1]);
                    MMA_F16(acc[nt1], Al[kt], b1[2 * kt], b1[2 * kt + 1]);
                }
            }
#pragma unroll
            for (int a = 0; a < 2; ++a) {
                float m0 = -1e30f, m1 = -1e30f;
#pragma unroll
                for (int nt = a * 4; nt < a * 4 + 4; ++nt) {
                    m0 = fmaxf(m0, fmaxf(acc[nt][0], acc[nt][1]));
                    m1 = fmaxf(m1, fmaxf(acc[nt][2], acc[nt][3]));
                }
                m0 = fmaxf(m0, __shfl_xor_sync(0xffffffffu, m0, 1));
                m0 = fmaxf(m0, __shfl_xor_sync(0xffffffffu, m0, 2));
                m1 = fmaxf(m1, __shfl_xor_sync(0xffffffffu, m1, 1));
                m1 = fmaxf(m1, __shfl_xor_sync(0xffffffffu, m1, 2));
                fsum[0][a] += fmaxf(m0, 0.f);
                fsum[1][a] += fmaxf(m1, 0.f);
            }
        }
        if (pair < 7) produce(pair + 1, buf ^ 1);
        if (q == 0) {
#pragma unroll
            for (int rh = 0; rh < 2; ++rh)
#pragma unroll
                for (int a = 0; a < 2; ++a) {
                    int o = 16 * w + 8 * rh + nl;
                    s_obuf[o * 16 + pair * 2 + a] = fsum[rh][a];
                }
        }
#pragma unroll
        for (int i = 0; i < 4; ++i) (&fsum[0][0])[i] = 0.f;
        __syncthreads();
    }

    if (tid < 128) {
        float4* dst = (float4*)(out + 24576 + ((size_t)g * C1 + tid) * MANCH + m_base);
        const float4* src = (const float4*)(s_obuf + tid * 16);
#pragma unroll
        for (int i = 0; i < 4; ++i) dst[i] = src[i];
    }
}

// ---------------------------------------------------------------------------
extern "C" void kernel_launch(void* const* d_in, const int* in_sizes, int n_in,
                              void* d_out, int out_size) {
    const float* xyzs = (const float*)d_in[0];
    const float* Wd   = (const float*)d_in[1];
    const float* Wm   = (const float*)d_in[2];
    float* out = (float*)d_out;

    cudaFuncSetAttribute(mlp_kernel, cudaFuncAttributeMaxDynamicSharedMemorySize,
                         2 * 3 * TILEB);

    fps_kernel<<<GROUPS, 128>>>(xyzs, out);
    ball_kernel<<<GROUPS * 3, 256>>>(xyzs, out);
    mlp_kernel<<<GROUPS * 8, 256, 2 * 3 * TILEB>>>(Wd, Wm, out);
}

// round 12
// speedup vs baseline: 1.1423x; 1.1423x over previous
#include <cuda_runtime.h>
#include <cuda_bf16.h>
#include <cuda_fp16.h>
#include <cstdint>

#define BATCH   4
#define TFRAMES 32
#define NPTS    4096
#define FOUT    16
#define GROUPS  64
#define MANCH   128
#define KNBR    32
#define C0      64
#define C1      128

__device__ float4 g_disp[3 * GROUPS * MANCH * KNBR];   // 12.58 MB scratch

typedef unsigned long long ull;

__device__ __forceinline__ ull fma2(ull a, ull b, ull c) {
    ull d;
    asm("fma.rn.f32x2 %0, %1, %2, %3;" : "=l"(d) : "l"(a), "l"(b), "l"(c));
    return d;
}
__device__ __forceinline__ ull packf(float lo, float hi) {
    ull r;
    asm("mov.b64 %0, {%1, %2};" : "=l"(r) : "f"(lo), "f"(hi));
    return r;
}
__device__ __forceinline__ void unpackf(ull v, float& lo, float& hi) {
    asm("mov.b64 {%0, %1}, %2;" : "=f"(lo), "=f"(hi) : "l"(v));
}

// ---------------------------------------------------------------------------
// Kernel 1: FPS (R9-proven). 128 threads, 32 pts/thread.
// ---------------------------------------------------------------------------
__global__ __launch_bounds__(128) void fps_kernel(const float* __restrict__ xyzs,
                                                  float* __restrict__ out_xyz) {
    const int g = blockIdx.x;
    const int b = g >> 4, f = g & 15;
    const float* fr = xyzs + ((size_t)(b * TFRAMES + 2 * f) * NPTS) * 3;
    const int tid = threadIdx.x;
    const int wid = tid >> 5, lane = tid & 31;

    __shared__ float sp[NPTS * 3];
    __shared__ ull wkey[2][4];
    for (int i = tid; i < NPTS * 3; i += 128) sp[i] = fr[i];
    __syncthreads();

    const ull ONE2 = packf(1.0f, 1.0f);
    ull px2[16], py2[16], pz2[16];
    float dist[32];
#pragma unroll
    for (int j = 0; j < 16; ++j) {
        int p0 = j * 256 + tid, p1 = p0 + 128;
        px2[j] = packf(sp[p0 * 3 + 0], sp[p1 * 3 + 0]);
        py2[j] = packf(sp[p0 * 3 + 1], sp[p1 * 3 + 1]);
        pz2[j] = packf(sp[p0 * 3 + 2], sp[p1 * 3 + 2]);
        dist[2 * j] = 1e10f; dist[2 * j + 1] = 1e10f;
    }

    float cx = sp[0], cy = sp[1], cz = sp[2];
    if (tid == 0) {
        float* o = out_xyz + (size_t)g * MANCH * 3;
        o[0] = cx; o[1] = cy; o[2] = cz;
    }

    for (int s = 1; s < MANCH; ++s) {
        const ull ncx2 = packf(-cx, -cx);
        const ull ncy2 = packf(-cy, -cy);
        const ull ncz2 = packf(-cz, -cz);
#pragma unroll
        for (int j = 0; j < 16; ++j) {
            ull ax = fma2(px2[j], ONE2, ncx2);
            ull ay = fma2(py2[j], ONE2, ncy2);
            ull az = fma2(pz2[j], ONE2, ncz2);
            ull mx = fma2(ax, ax, 0ull);
            ull my = fma2(ay, ay, 0ull);
            ull s1 = fma2(mx, ONE2, my);
            ull mz = fma2(az, az, 0ull);
            ull d2 = fma2(s1, ONE2, mz);
            float dlo, dhi;
            unpackf(d2, dlo, dhi);
            dist[2 * j]     = fminf(dist[2 * j], dlo);
            dist[2 * j + 1] = fminf(dist[2 * j + 1], dhi);
        }
        float t[16];
#pragma unroll
        for (int i = 0; i < 16; ++i) t[i] = fmaxf(dist[2 * i], dist[2 * i + 1]);
#pragma unroll
        for (int st = 8; st; st >>= 1)
#pragma unroll
            for (int i = 0; i < 8; ++i)
                if (i < st) t[i] = fmaxf(t[i], t[i + st]);
        unsigned wmax = __reduce_max_sync(0xffffffffu, __float_as_uint(t[0]));
        float wvf = __uint_as_float(wmax);
        unsigned cand = 0xffffffffu;
#pragma unroll
        for (int sl = 0; sl < 32; ++sl) {
            unsigned gi = (sl >> 1) * 256 + (sl & 1) * 128 + tid;
            if (dist[sl] == wvf) cand = min(cand, gi);
        }
        cand = __reduce_min_sync(0xffffffffu, cand);
        if (lane == 0)
            wkey[s & 1][wid] = ((ull)wmax << 32) | (unsigned)(~cand);
        __syncthreads();
        const ull* kk = wkey[s & 1];
        ull best = max(max(kk[0], kk[1]), max(kk[2], kk[3]));
        int wi = (int)(~(unsigned)best);
        cx = sp[wi * 3 + 0]; cy = sp[wi * 3 + 1]; cz = sp[wi * 3 + 2];
        if (tid == 0) {
            float* o = out_xyz + ((size_t)g * MANCH + s) * 3;
            o[0] = cx; o[1] = cy; o[2] = cz;
        }
    }
}

// ---------------------------------------------------------------------------
// Kernel 2: ball query (unchanged; proven)
// ---------------------------------------------------------------------------
__global__ __launch_bounds__(256) void ball_kernel(const float* __restrict__ xyzs,
                                                   const float* __restrict__ anchors) {
    const int bid = blockIdx.x;
    const int g = bid / 3, dti = bid % 3;
    const int dt = dti - 1;
    const int b = g >> 4, f = g & 15;
    int t = 2 * f + dt;
    t = min(max(t, 0), TFRAMES - 1);
    const float* fr = xyzs + (size_t)(b * TFRAMES + t) * NPTS * 3;

    __shared__ float sx[NPTS], sy[NPTS], sz[NPTS];
    for (int p = threadIdx.x; p < NPTS; p += 256) {
        const float* pp = fr + p * 3;
        sx[p] = pp[0]; sy[p] = pp[1]; sz[p] = pp[2];
    }
    __syncthreads();

    const int w = threadIdx.x >> 5;
    const int lane = threadIdx.x & 31;
    const float r2 = (float)(0.15 * 0.15);
    const float tch = (float)dt;
    const ull ONE2 = packf(1.0f, 1.0f);
    const unsigned below = (1u << lane) - 1u;

    for (int m = w; m < MANCH; m += 8) {
        const float* a = anchors + ((size_t)g * MANCH + m) * 3;
        const float ax = a[0], ay = a[1], az = a[2];
        const ull nax2 = packf(-ax, -ax);
        const ull nay2 = packf(-ay, -ay);
        const ull naz2 = packf(-az, -az);
        float4* od = g_disp + ((size_t)(dti * GROUPS + g) * MANCH + m) * KNBR;

        int filled = 0;
        int firstidx = -1;

        for (int base = 0; base < NPTS; base += 128) {
            const int j0 = base + 4 * lane;
            float4 X = *(const float4*)(sx + j0);
            float4 Y = *(const float4*)(sy + j0);
            float4 Z = *(const float4*)(sz + j0);
            ull dxa = fma2(packf(X.x, X.y), ONE2, nax2);
            ull dxb = fma2(packf(X.z, X.w), ONE2, nax2);
            ull dya = fma2(packf(Y.x, Y.y), ONE2, nay2);
            ull dyb = fma2(packf(Y.z, Y.w), ONE2, nay2);
            ull dza = fma2(packf(Z.x, Z.y), ONE2, naz2);
            ull dzb = fma2(packf(Z.z, Z.w), ONE2, naz2);
            ull s1a = fma2(fma2(dxa, dxa, 0ull), ONE2, fma2(dya, dya, 0ull));
            ull s1b = fma2(fma2(dxb, dxb, 0ull), ONE2, fma2(dyb, dyb, 0ull));
            ull d2a = fma2(s1a, ONE2, fma2(dza, dza, 0ull));
            ull d2b = fma2(s1b, ONE2, fma2(dzb, dzb, 0ull));
            float d0, d1, d2, d3;
            unpackf(d2a, d0, d1);
            unpackf(d2b, d2, d3);
            bool p0 = d0 < r2, p1 = d1 < r2, p2 = d2 < r2, p3 = d3 < r2;
            unsigned m0 = __ballot_sync(0xffffffffu, p0);
            unsigned m1 = __ballot_sync(0xffffffffu, p1);
            unsigned m2 = __ballot_sync(0xffffffffu, p2);
            unsigned m3 = __ballot_sync(0xffffffffu, p3);
            unsigned anyh = m0 | m1 | m2 | m3;
            if (anyh) {
                int pos = filled + __popc(m0 & below) + __popc(m1 & below)
                                 + __popc(m2 & below) + __popc(m3 & below);
                float x0, x1, y0, y1, z0, z1, x2, x3, y2, y3, z2, z3;
                unpackf(dxa, x0, x1); unpackf(dya, y0, y1); unpackf(dza, z0, z1);
                unpackf(dxb, x2, x3); unpackf(dyb, y2, y3); unpackf(dzb, z2, z3);
                if (p0) { if (pos < KNBR) od[pos] = make_float4(x0, y0, z0, tch); pos++; }
                if (p1) { if (pos < KNBR) od[pos] = make_float4(x1, y1, z1, tch); pos++; }
                if (p2) { if (pos < KNBR) od[pos] = make_float4(x2, y2, z2, tch); pos++; }
                if (p3) { if (pos < KNBR) od[pos] = make_float4(x3, y3, z3, tch); pos++; }
                if (firstidx < 0) {
                    unsigned i0 = m0 ? 4u * (__ffs(m0) - 1)     : 0xffffu;
                    unsigned i1 = m1 ? 4u * (__ffs(m1) - 1) + 1 : 0xffffu;
                    unsigned i2 = m2 ? 4u * (__ffs(m2) - 1) + 2 : 0xffffu;
                    unsigned i3 = m3 ? 4u * (__ffs(m3) - 1) + 3 : 0xffffu;
                    firstidx = base + (int)min(min(i0, i1), min(i2, i3));
                }
                filled += __popc(m0) + __popc(m1) + __popc(m2) + __popc(m3);
                if (filled >= KNBR) break;
            }
        }
        if (filled < KNBR) {
            int fi = (firstidx < 0) ? 0 : firstidx;
            float fx = sx[fi] - ax, fy = sy[fi] - ay, fz = sz[fi] - az;
            int s = filled + lane;
            if (s < KNBR) od[s] = make_float4(fx, fy, fz, tch);
        }
    }
}

// ---------------------------------------------------------------------------
// Kernel 3: MLP (R9 128-thread version) + g_disp LDG prefetch across consumes.
// ---------------------------------------------------------------------------
#define HBW 36
#define TILEW (64 * HBW)
#define TILEB (TILEW * 4)

#define MMA_F16(d, a, b0, b1)                                                   \
    asm("mma.sync.aligned.m16n8k16.row.col.f32.f16.f16.f32 "                    \
        "{%0,%1,%2,%3}, {%4,%5,%6,%7}, {%8,%9}, {%0,%1,%2,%3};"                 \
        : "+f"((d)[0]), "+f"((d)[1]), "+f"((d)[2]), "+f"((d)[3])                \
        : "r"((a)[0]), "r"((a)[1]), "r"((a)[2]), "r"((a)[3]), "r"(b0), "r"(b1))

#define LDM_X4(r0, r1, r2, r3, addr)                                            \
    asm volatile("ldmatrix.sync.aligned.m8n8.x4.shared.b16 {%0,%1,%2,%3}, [%4];" \
        : "=r"(r0), "=r"(r1), "=r"(r2), "=r"(r3) : "r"(addr))

__global__ __launch_bounds__(128, 2) void mlp_kernel(const float* __restrict__ Wd,
                                                     const float* __restrict__ Wm,
                                                     float* __restrict__ out) {
    extern __shared__ __align__(16) uint32_t s_hb[];        // [2][3][TILEW]
    __shared__ __align__(16) ull s_wdp[2][16][4];
    __shared__ float s_obuf[C1 * 16];

    const int tid = threadIdx.x;
    const int w = tid >> 5, lane = tid & 31;
    const int q = lane & 3, nl = lane >> 2;
    const int g = blockIdx.x >> 3;
    const int m_base = (blockIdx.x & 7) * 16;

    {
        const int h = tid >> 6, j = (tid >> 2) & 15, c = tid & 3;
        const int c0 = 32 * h + 2 * j;
        s_wdp[h][j][c] = packf(Wd[c0 * 4 + c], Wd[(c0 + 1) * 4 + c]);
    }

    uint32_t Ah[2][4][4], Al[2][4][4];
#pragma unroll
    for (int rr = 0; rr < 4; ++rr) {
        const int r = 32 * w + 16 * (rr >> 1) + 8 * (rr & 1) + nl;
        const float* wr = Wm + (size_t)r * C0;
#pragma unroll
        for (int kt = 0; kt < 4; ++kt)
#pragma unroll
            for (int hf = 0; hf < 2; ++hf) {
                float2 v = *(const float2*)(wr + kt * 16 + 8 * hf + 2 * q);
                __half2 h2 = __floats2half2_rn(v.x, v.y);
                __half2 l2 = __floats2half2_rn(v.x - __low2float(h2),
                                               v.y - __high2float(h2));
                Ah[rr >> 1][kt][(rr & 1) + 2 * hf] = *(uint32_t*)&h2;
                Al[rr >> 1][kt][(rr & 1) + 2 * hf] = *(uint32_t*)&l2;
            }
    }
    __syncthreads();

    const int l1_a  = tid >> 6;
    const int l1_k  = (tid >> 1) & 31;
    const int l1_ch = tid & 1;
    const int prow  = l1_a * 32 + l1_k;
    const ull* wp = &s_wdp[l1_ch][0][0];

    const uint32_t hb0 = (uint32_t)__cvta_generic_to_shared(&s_hb[0]);
    const uint32_t laneoff = (uint32_t)((lane & 7) * (HBW * 4) + (lane >> 3) * 16);

    auto load_dv = [&](int pair, float4* dv) {
        const int m = m_base + pair * 2 + l1_a;
#pragma unroll
        for (int sub = 0; sub < 3; ++sub)
            dv[sub] = g_disp[((size_t)(sub * GROUPS + g) * MANCH + m) * KNBR + l1_k];
    };
    auto store_h = [&](const float4* dv, int buf) {
#pragma unroll
        for (int sub = 0; sub < 3; ++sub) {
            const ull dvx2 = packf(dv[sub].x, dv[sub].x);
            const ull dvy2 = packf(dv[sub].y, dv[sub].y);
            const ull dvz2 = packf(dv[sub].z, dv[sub].z);
            const ull dvw2 = packf(dv[sub].w, dv[sub].w);
            uint32_t* hrow = &s_hb[(buf * 3 + sub) * TILEW + prow * HBW + l1_ch * 16];
#pragma unroll
            for (int j = 0; j < 16; ++j) {
                ull acc = fma2(wp[4 * j + 0], dvx2, 0ull);
                acc = fma2(wp[4 * j + 1], dvy2, acc);
                acc = fma2(wp[4 * j + 2], dvz2, acc);
                acc = fma2(wp[4 * j + 3], dvw2, acc);
                float h0, h1;
                unpackf(acc, h0, h1);
                __half2 p = __floats2half2_rn(fmaxf(h0, 0.f), fmaxf(h1, 0.f));
                hrow[j] = *(uint32_t*)&p;
            }
        }
    };

    float fsum[2][2][2];
#pragma unroll
    for (int i = 0; i < 8; ++i) (&fsum[0][0][0])[i] = 0.f;

    {
        float4 dv0[3];
        load_dv(0, dv0);
        store_h(dv0, 0);
    }
    __syncthreads();

    for (int pair = 0; pair < 8; ++pair) {
        const int buf = pair & 1;
        float4 dvn[3];
        if (pair < 7) load_dv(pair + 1, dvn);   // prefetch: hidden by consumes
#pragma unroll
        for (int sub = 0; sub < 3; ++sub) {
            float acc[2][8][4];
#pragma unroll
            for (int i = 0; i < 64; ++i) (&acc[0][0][0])[i] = 0.f;
            const uint32_t ab = hb0 + (uint32_t)(buf * 3 + sub) * TILEB + laneoff;
#pragma unroll
            for (int ntp = 0; ntp < 4; ++ntp) {
                const int nt0 = 2 * ntp, nt1 = nt0 + 1;
                uint32_t b0[8], b1[8];
                const uint32_t r0 = (uint32_t)(nt0 * 8 * HBW * 4);
                const uint32_t r1 = (uint32_t)(nt1 * 8 * HBW * 4);
                LDM_X4(b0[0], b0[1], b0[2], b0[3], ab + r0);
                LDM_X4(b0[4], b0[5], b0[6], b0[7], ab + r0 + 64);
                LDM_X4(b1[0], b1[1], b1[2], b1[3], ab + r1);
                LDM_X4(b1[4], b1[5], b1[6], b1[7], ab + r1 + 64);
#pragma unroll
                for (int kt = 0; kt < 4; ++kt) {
#pragma unroll
                    for (int mt = 0; mt < 2; ++mt) {
                        MMA_F16(acc[mt][nt0], Ah[mt][kt], b0[2 * kt], b0[2 * kt + 1]);
                        MMA_F16(acc[mt][nt1], Ah[mt][kt], b1[2 * kt], b1[2 * kt + 1]);
                        MMA_F16(acc[mt][nt0], Al[mt][kt], b0[2 * kt], b0[2 * kt + 1]);
                        MMA_F16(acc[mt][nt1], Al[mt][kt], b1[2 * kt], b1[2 * kt + 1]);
                    }
                }
            }
#pragma unroll
            for (int mt = 0; mt < 2; ++mt)
#pragma unroll
                for (int a = 0; a < 2; ++a) {
                    float m0 = -1e30f, m1 = -1e30f;
#pragma unroll
                    for (int nt = a * 4; nt < a * 4 + 4; ++nt) {
                        m0 = fmaxf(m0, fmaxf(acc[mt][nt][0], acc[mt][nt][1]));
                        m1 = fmaxf(m1, fmaxf(acc[mt][nt][2], acc[mt][nt][3]));
                    }
                    m0 = fmaxf(m0, __shfl_xor_sync(0xffffffffu, m0, 1));
                    m0 = fmaxf(m0, __shfl_xor_sync(0xffffffffu, m0, 2));
                    m1 = fmaxf(m1, __shfl_xor_sync(0xffffffffu, m1, 1));
                    m1 = fmaxf(m1, __shfl_xor_sync(0xffffffffu, m1, 2));
                    fsum[mt][0][a] += fmaxf(m0, 0.f);
                    fsum[mt][1][a] += fmaxf(m1, 0.f);
                }
        }
        if (pair < 7) store_h(dvn, buf ^ 1);
        if (q == 0) {
#pragma unroll
            for (int mt = 0; mt < 2; ++mt)
#pragma unroll
                for (int rh = 0; rh < 2; ++rh)
#pragma unroll
                    for (int a = 0; a < 2; ++a) {
                        int o = 32 * w + 16 * mt + 8 * rh + nl;
                        s_obuf[o * 16 + pair * 2 + a] = fsum[mt][rh][a];
                    }
        }
#pragma unroll
        for (int i = 0; i < 8; ++i) (&fsum[0][0][0])[i] = 0.f;
        __syncthreads();
    }

    float4* dst = (float4*)(out + 24576 + ((size_t)g * C1 + tid) * MANCH + m_base);
    const float4* src = (const float4*)(s_obuf + tid * 16);
#pragma unroll
    for (int i = 0; i < 4; ++i) dst[i] = src[i];
}

// ---------------------------------------------------------------------------
extern "C" void kernel_launch(void* const* d_in, const int* in_sizes, int n_in,
                              void* d_out, int out_size) {
    const float* xyzs = (const float*)d_in[0];
    const float* Wd   = (const float*)d_in[1];
    const float* Wm   = (const float*)d_in[2];
    float* out = (float*)d_out;

    cudaFuncSetAttribute(mlp_kernel, cudaFuncAttributeMaxDynamicSharedMemorySize,
                         2 * 3 * TILEB);

    fps_kernel<<<GROUPS, 128>>>(xyzs, out);
    ball_kernel<<<GROUPS * 3, 256>>>(xyzs, out);
    mlp_kernel<<<GROUPS * 8, 128, 2 * 3 * TILEB>>>(Wd, Wm, out);
}

// round 13
// speedup vs baseline: 1.2641x; 1.1066x over previous
#include <cuda_runtime.h>
#include <cuda_bf16.h>
#include <cuda_fp16.h>
#include <cstdint>

#define BATCH   4
#define TFRAMES 32
#define NPTS    4096
#define FOUT    16
#define GROUPS  64
#define MANCH   128
#define KNBR    32
#define C0      64
#define C1      128

__device__ float4 g_disp[3 * GROUPS * MANCH * KNBR];   // 12.58 MB scratch

typedef unsigned long long ull;

__device__ __forceinline__ ull fma2(ull a, ull b, ull c) {
    ull d;
    asm("fma.rn.f32x2 %0, %1, %2, %3;" : "=l"(d) : "l"(a), "l"(b), "l"(c));
    return d;
}
__device__ __forceinline__ ull packf(float lo, float hi) {
    ull r;
    asm("mov.b64 %0, {%1, %2};" : "=l"(r) : "f"(lo), "f"(hi));
    return r;
}
__device__ __forceinline__ void unpackf(ull v, float& lo, float& hi) {
    asm("mov.b64 {%0, %1}, %2;" : "=f"(lo), "=f"(hi) : "l"(v));
}

// ---------------------------------------------------------------------------
// Kernel 1: FPS (R9-proven). 128 threads, 32 pts/thread.
// ---------------------------------------------------------------------------
__global__ __launch_bounds__(128) void fps_kernel(const float* __restrict__ xyzs,
                                                  float* __restrict__ out_xyz) {
    const int g = blockIdx.x;
    const int b = g >> 4, f = g & 15;
    const float* fr = xyzs + ((size_t)(b * TFRAMES + 2 * f) * NPTS) * 3;
    const int tid = threadIdx.x;
    const int wid = tid >> 5, lane = tid & 31;

    __shared__ float sp[NPTS * 3];
    __shared__ ull wkey[2][4];
    for (int i = tid; i < NPTS * 3; i += 128) sp[i] = fr[i];
    __syncthreads();

    const ull ONE2 = packf(1.0f, 1.0f);
    ull px2[16], py2[16], pz2[16];
    float dist[32];
#pragma unroll
    for (int j = 0; j < 16; ++j) {
        int p0 = j * 256 + tid, p1 = p0 + 128;
        px2[j] = packf(sp[p0 * 3 + 0], sp[p1 * 3 + 0]);
        py2[j] = packf(sp[p0 * 3 + 1], sp[p1 * 3 + 1]);
        pz2[j] = packf(sp[p0 * 3 + 2], sp[p1 * 3 + 2]);
        dist[2 * j] = 1e10f; dist[2 * j + 1] = 1e10f;
    }

    float cx = sp[0], cy = sp[1], cz = sp[2];
    if (tid == 0) {
        float* o = out_xyz + (size_t)g * MANCH * 3;
        o[0] = cx; o[1] = cy; o[2] = cz;
    }

    for (int s = 1; s < MANCH; ++s) {
        const ull ncx2 = packf(-cx, -cx);
        const ull ncy2 = packf(-cy, -cy);
        const ull ncz2 = packf(-cz, -cz);
#pragma unroll
        for (int j = 0; j < 16; ++j) {
            ull ax = fma2(px2[j], ONE2, ncx2);
            ull ay = fma2(py2[j], ONE2, ncy2);
            ull az = fma2(pz2[j], ONE2, ncz2);
            ull mx = fma2(ax, ax, 0ull);
            ull my = fma2(ay, ay, 0ull);
            ull s1 = fma2(mx, ONE2, my);
            ull mz = fma2(az, az, 0ull);
            ull d2 = fma2(s1, ONE2, mz);
            float dlo, dhi;
            unpackf(d2, dlo, dhi);
            dist[2 * j]     = fminf(dist[2 * j], dlo);
            dist[2 * j + 1] = fminf(dist[2 * j + 1], dhi);
        }
        float t[16];
#pragma unroll
        for (int i = 0; i < 16; ++i) t[i] = fmaxf(dist[2 * i], dist[2 * i + 1]);
#pragma unroll
        for (int st = 8; st; st >>= 1)
#pragma unroll
            for (int i = 0; i < 8; ++i)
                if (i < st) t[i] = fmaxf(t[i], t[i + st]);
        unsigned wmax = __reduce_max_sync(0xffffffffu, __float_as_uint(t[0]));
        float wvf = __uint_as_float(wmax);
        unsigned cand = 0xffffffffu;
#pragma unroll
        for (int sl = 0; sl < 32; ++sl) {
            unsigned gi = (sl >> 1) * 256 + (sl & 1) * 128 + tid;
            if (dist[sl] == wvf) cand = min(cand, gi);
        }
        cand = __reduce_min_sync(0xffffffffu, cand);
        if (lane == 0)
            wkey[s & 1][wid] = ((ull)wmax << 32) | (unsigned)(~cand);
        __syncthreads();
        const ull* kk = wkey[s & 1];
        ull best = max(max(kk[0], kk[1]), max(kk[2], kk[3]));
        int wi = (int)(~(unsigned)best);
        cx = sp[wi * 3 + 0]; cy = sp[wi * 3 + 1]; cz = sp[wi * 3 + 2];
        if (tid == 0) {
            float* o = out_xyz + ((size_t)g * MANCH + s) * 3;
            o[0] = cx; o[1] = cy; o[2] = cz;
        }
    }
}

// ---------------------------------------------------------------------------
// Kernel 2: ball query (unchanged; proven)
// ---------------------------------------------------------------------------
__global__ __launch_bounds__(256) void ball_kernel(const float* __restrict__ xyzs,
                                                   const float* __restrict__ anchors) {
    const int bid = blockIdx.x;
    const int g = bid / 3, dti = bid % 3;
    const int dt = dti - 1;
    const int b = g >> 4, f = g & 15;
    int t = 2 * f + dt;
    t = min(max(t, 0), TFRAMES - 1);
    const float* fr = xyzs + (size_t)(b * TFRAMES + t) * NPTS * 3;

    __shared__ float sx[NPTS], sy[NPTS], sz[NPTS];
    for (int p = threadIdx.x; p < NPTS; p += 256) {
        const float* pp = fr + p * 3;
        sx[p] = pp[0]; sy[p] = pp[1]; sz[p] = pp[2];
    }
    __syncthreads();

    const int w = threadIdx.x >> 5;
    const int lane = threadIdx.x & 31;
    const float r2 = (float)(0.15 * 0.15);
    const float tch = (float)dt;
    const ull ONE2 = packf(1.0f, 1.0f);
    const unsigned below = (1u << lane) - 1u;

    for (int m = w; m < MANCH; m += 8) {
        const float* a = anchors + ((size_t)g * MANCH + m) * 3;
        const float ax = a[0], ay = a[1], az = a[2];
        const ull nax2 = packf(-ax, -ax);
        const ull nay2 = packf(-ay, -ay);
        const ull naz2 = packf(-az, -az);
        float4* od = g_disp + ((size_t)(dti * GROUPS + g) * MANCH + m) * KNBR;

        int filled = 0;
        int firstidx = -1;

        for (int base = 0; base < NPTS; base += 128) {
            const int j0 = base + 4 * lane;
            float4 X = *(const float4*)(sx + j0);
            float4 Y = *(const float4*)(sy + j0);
            float4 Z = *(const float4*)(sz + j0);
            ull dxa = fma2(packf(X.x, X.y), ONE2, nax2);
            ull dxb = fma2(packf(X.z, X.w), ONE2, nax2);
            ull dya = fma2(packf(Y.x, Y.y), ONE2, nay2);
            ull dyb = fma2(packf(Y.z, Y.w), ONE2, nay2);
            ull dza = fma2(packf(Z.x, Z.y), ONE2, naz2);
            ull dzb = fma2(packf(Z.z, Z.w), ONE2, naz2);
            ull s1a = fma2(fma2(dxa, dxa, 0ull), ONE2, fma2(dya, dya, 0ull));
            ull s1b = fma2(fma2(dxb, dxb, 0ull), ONE2, fma2(dyb, dyb, 0ull));
            ull d2a = fma2(s1a, ONE2, fma2(dza, dza, 0ull));
            ull d2b = fma2(s1b, ONE2, fma2(dzb, dzb, 0ull));
            float d0, d1, d2, d3;
            unpackf(d2a, d0, d1);
            unpackf(d2b, d2, d3);
            bool p0 = d0 < r2, p1 = d1 < r2, p2 = d2 < r2, p3 = d3 < r2;
            unsigned m0 = __ballot_sync(0xffffffffu, p0);
            unsigned m1 = __ballot_sync(0xffffffffu, p1);
            unsigned m2 = __ballot_sync(0xffffffffu, p2);
            unsigned m3 = __ballot_sync(0xffffffffu, p3);
            unsigned anyh = m0 | m1 | m2 | m3;
            if (anyh) {
                int pos = filled + __popc(m0 & below) + __popc(m1 & below)
                                 + __popc(m2 & below) + __popc(m3 & below);
                float x0, x1, y0, y1, z0, z1, x2, x3, y2, y3, z2, z3;
                unpackf(dxa, x0, x1); unpackf(dya, y0, y1); unpackf(dza, z0, z1);
                unpackf(dxb, x2, x3); unpackf(dyb, y2, y3); unpackf(dzb, z2, z3);
                if (p0) { if (pos < KNBR) od[pos] = make_float4(x0, y0, z0, tch); pos++; }
                if (p1) { if (pos < KNBR) od[pos] = make_float4(x1, y1, z1, tch); pos++; }
                if (p2) { if (pos < KNBR) od[pos] = make_float4(x2, y2, z2, tch); pos++; }
                if (p3) { if (pos < KNBR) od[pos] = make_float4(x3, y3, z3, tch); pos++; }
                if (firstidx < 0) {
                    unsigned i0 = m0 ? 4u * (__ffs(m0) - 1)     : 0xffffu;
                    unsigned i1 = m1 ? 4u * (__ffs(m1) - 1) + 1 : 0xffffu;
                    unsigned i2 = m2 ? 4u * (__ffs(m2) - 1) + 2 : 0xffffu;
                    unsigned i3 = m3 ? 4u * (__ffs(m3) - 1) + 3 : 0xffffu;
                    firstidx = base + (int)min(min(i0, i1), min(i2, i3));
                }
                filled += __popc(m0) + __popc(m1) + __popc(m2) + __popc(m3);
                if (filled >= KNBR) break;
            }
        }
        if (filled < KNBR) {
            int fi = (firstidx < 0) ? 0 : firstidx;
            float fx = sx[fi] - ax, fy = sy[fi] - ay, fz = sz[fi] - az;
            int s = filled + lane;
            if (s < KNBR) od[s] = make_float4(fx, fy, fz, tch);
        }
    }
}

// ---------------------------------------------------------------------------
// Kernel 3: MLP (R9 structure), SINGLE-pass fp16 MMA (Wm rounded once).
// ---------------------------------------------------------------------------
#define HBW 36
#define TILEW (64 * HBW)
#define TILEB (TILEW * 4)

#define MMA_F16(d, a, b0, b1)                                                   \
    asm("mma.sync.aligned.m16n8k16.row.col.f32.f16.f16.f32 "                    \
        "{%0,%1,%2,%3}, {%4,%5,%6,%7}, {%8,%9}, {%0,%1,%2,%3};"                 \
        : "+f"((d)[0]), "+f"((d)[1]), "+f"((d)[2]), "+f"((d)[3])                \
        : "r"((a)[0]), "r"((a)[1]), "r"((a)[2]), "r"((a)[3]), "r"(b0), "r"(b1))

#define LDM_X4(r0, r1, r2, r3, addr)                                            \
    asm volatile("ldmatrix.sync.aligned.m8n8.x4.shared.b16 {%0,%1,%2,%3}, [%4];" \
        : "=r"(r0), "=r"(r1), "=r"(r2), "=r"(r3) : "r"(addr))

__global__ __launch_bounds__(128, 2) void mlp_kernel(const float* __restrict__ Wd,
                                                     const float* __restrict__ Wm,
                                                     float* __restrict__ out) {
    extern __shared__ __align__(16) uint32_t s_hb[];        // [2][3][TILEW]
    __shared__ __align__(16) ull s_wdp[2][16][4];
    __shared__ float s_obuf[C1 * 16];

    const int tid = threadIdx.x;
    const int w = tid >> 5, lane = tid & 31;
    const int q = lane & 3, nl = lane >> 2;
    const int g = blockIdx.x >> 3;
    const int m_base = (blockIdx.x & 7) * 16;

    {
        const int h = tid >> 6, j = (tid >> 2) & 15, c = tid & 3;
        const int c0 = 32 * h + 2 * j;
        s_wdp[h][j][c] = packf(Wd[c0 * 4 + c], Wd[(c0 + 1) * 4 + c]);
    }

    uint32_t Ah[2][4][4];
#pragma unroll
    for (int rr = 0; rr < 4; ++rr) {
        const int r = 32 * w + 16 * (rr >> 1) + 8 * (rr & 1) + nl;
        const float* wr = Wm + (size_t)r * C0;
#pragma unroll
        for (int kt = 0; kt < 4; ++kt)
#pragma unroll
            for (int hf = 0; hf < 2; ++hf) {
                float2 v = *(const float2*)(wr + kt * 16 + 8 * hf + 2 * q);
                __half2 h2 = __floats2half2_rn(v.x, v.y);
                Ah[rr >> 1][kt][(rr & 1) + 2 * hf] = *(uint32_t*)&h2;
            }
    }
    __syncthreads();

    const int l1_a  = tid >> 6;
    const int l1_k  = (tid >> 1) & 31;
    const int l1_ch = tid & 1;
    const int prow  = l1_a * 32 + l1_k;
    const ull* wp = &s_wdp[l1_ch][0][0];

    const uint32_t hb0 = (uint32_t)__cvta_generic_to_shared(&s_hb[0]);
    const uint32_t laneoff = (uint32_t)((lane & 7) * (HBW * 4) + (lane >> 3) * 16);

    auto produce = [&](int pair, int buf) {
        const int m = m_base + pair * 2 + l1_a;
        float4 dv[3];
#pragma unroll
        for (int sub = 0; sub < 3; ++sub)
            dv[sub] = g_disp[((size_t)(sub * GROUPS + g) * MANCH + m) * KNBR + l1_k];
#pragma unroll
        for (int sub = 0; sub < 3; ++sub) {
            const ull dvx2 = packf(dv[sub].x, dv[sub].x);
            const ull dvy2 = packf(dv[sub].y, dv[sub].y);
            const ull dvz2 = packf(dv[sub].z, dv[sub].z);
            const ull dvw2 = packf(dv[sub].w, dv[sub].w);
            uint32_t* hrow = &s_hb[(buf * 3 + sub) * TILEW + prow * HBW + l1_ch * 16];
#pragma unroll
            for (int j = 0; j < 16; ++j) {
                ull acc = fma2(wp[4 * j + 0], dvx2, 0ull);
                acc = fma2(wp[4 * j + 1], dvy2, acc);
                acc = fma2(wp[4 * j + 2], dvz2, acc);
                acc = fma2(wp[4 * j + 3], dvw2, acc);
                float h0, h1;
                unpackf(acc, h0, h1);
                __half2 p = __floats2half2_rn(fmaxf(h0, 0.f), fmaxf(h1, 0.f));
                hrow[j] = *(uint32_t*)&p;
            }
        }
    };

    float fsum[2][2][2];
#pragma unroll
    for (int i = 0; i < 8; ++i) (&fsum[0][0][0])[i] = 0.f;

    produce(0, 0);
    __syncthreads();

    for (int pair = 0; pair < 8; ++pair) {
        const int buf = pair & 1;
#pragma unroll
        for (int sub = 0; sub < 3; ++sub) {
            float acc[2][8][4];
#pragma unroll
            for (int i = 0; i < 64; ++i) (&acc[0][0][0])[i] = 0.f;
            const uint32_t ab = hb0 + (uint32_t)(buf * 3 + sub) * TILEB + laneoff;
#pragma unroll
            for (int ntp = 0; ntp < 4; ++ntp) {
                const int nt0 = 2 * ntp, nt1 = nt0 + 1;
                uint32_t b0[8], b1[8];
                const uint32_t r0 = (uint32_t)(nt0 * 8 * HBW * 4);
                const uint32_t r1 = (uint32_t)(nt1 * 8 * HBW * 4);
                LDM_X4(b0[0], b0[1], b0[2], b0[3], ab + r0);
                LDM_X4(b0[4], b0[5], b0[6], b0[7], ab + r0 + 64);
                LDM_X4(b1[0], b1[1], b1[2], b1[3], ab + r1);
                LDM_X4(b1[4], b1[5], b1[6], b1[7], ab + r1 + 64);
#pragma unroll
                for (int kt = 0; kt < 4; ++kt) {
#pragma unroll
                    for (int mt = 0; mt < 2; ++mt) {
                        MMA_F16(acc[mt][nt0], Ah[mt][kt], b0[2 * kt], b0[2 * kt + 1]);
                        MMA_F16(acc[mt][nt1], Ah[mt][kt], b1[2 * kt], b1[2 * kt + 1]);
                    }
                }
            }
#pragma unroll
            for (int mt = 0; mt < 2; ++mt)
#pragma unroll
                for (int a = 0; a < 2; ++a) {
                    float m0 = -1e30f, m1 = -1e30f;
#pragma unroll
                    for (int nt = a * 4; nt < a * 4 + 4; ++nt) {
                        m0 = fmaxf(m0, fmaxf(acc[mt][nt][0], acc[mt][nt][1]));
                        m1 = fmaxf(m1, fmaxf(acc[mt][nt][2], acc[mt][nt][3]));
                    }
                    m0 = fmaxf(m0, __shfl_xor_sync(0xffffffffu, m0, 1));
                    m0 = fmaxf(m0, __shfl_xor_sync(0xffffffffu, m0, 2));
                    m1 = fmaxf(m1, __shfl_xor_sync(0xffffffffu, m1, 1));
                    m1 = fmaxf(m1, __shfl_xor_sync(0xffffffffu, m1, 2));
                    fsum[mt][0][a] += fmaxf(m0, 0.f);
                    fsum[mt][1][a] += fmaxf(m1, 0.f);
                }
        }
        if (pair < 7) produce(pair + 1, buf ^ 1);
        if (q == 0) {
#pragma unroll
            for (int mt = 0; mt < 2; ++mt)
#pragma unroll
                for (int rh = 0; rh < 2; ++rh)
#pragma unroll
                    for (int a = 0; a < 2; ++a) {
                        int o = 32 * w + 16 * mt + 8 * rh + nl;
                        s_obuf[o * 16 + pair * 2 + a] = fsum[mt][rh][a];
                    }
        }
#pragma unroll
        for (int i = 0; i < 8; ++i) (&fsum[0][0][0])[i] = 0.f;
        __syncthreads();
    }

    float4* dst = (float4*)(out + 24576 + ((size_t)g * C1 + tid) * MANCH + m_base);
    const float4* src = (const float4*)(s_obuf + tid * 16);
#pragma unroll
    for (int i = 0; i < 4; ++i) dst[i] = src[i];
}

// ---------------------------------------------------------------------------
extern "C" void kernel_launch(void* const* d_in, const int* in_sizes, int n_in,
                              void* d_out, int out_size) {
    const float* xyzs = (const float*)d_in[0];
    const float* Wd   = (const float*)d_in[1];
    const float* Wm   = (const float*)d_in[2];
    float* out = (float*)d_out;

    cudaFuncSetAttribute(mlp_kernel, cudaFuncAttributeMaxDynamicSharedMemorySize,
                         2 * 3 * TILEB);

    fps_kernel<<<GROUPS, 128>>>(xyzs, out);
    ball_kernel<<<GROUPS * 3, 256>>>(xyzs, out);
    mlp_kernel<<<GROUPS * 8, 128, 2 * 3 * TILEB>>>(Wd, Wm, out);
}

// round 14
// speedup vs baseline: 1.2712x; 1.0056x over previous
#include <cuda_runtime.h>
#include <cuda_bf16.h>
#include <cuda_fp16.h>
#include <cstdint>

#define BATCH   4
#define TFRAMES 32
#define NPTS    4096
#define FOUT    16
#define GROUPS  64
#define MANCH   128
#define KNBR    32
#define C0      64
#define C1      128

__device__ float4 g_disp[3 * GROUPS * MANCH * KNBR];   // 12.58 MB scratch

typedef unsigned long long ull;

__device__ __forceinline__ ull fma2(ull a, ull b, ull c) {
    ull d;
    asm("fma.rn.f32x2 %0, %1, %2, %3;" : "=l"(d) : "l"(a), "l"(b), "l"(c));
    return d;
}
__device__ __forceinline__ ull packf(float lo, float hi) {
    ull r;
    asm("mov.b64 %0, {%1, %2};" : "=l"(r) : "f"(lo), "f"(hi));
    return r;
}
__device__ __forceinline__ void unpackf(ull v, float& lo, float& hi) {
    asm("mov.b64 {%0, %1}, %2;" : "=f"(lo), "=f"(hi) : "l"(v));
}

// ---------------------------------------------------------------------------
// Kernel 1: FPS (R9-proven). 128 threads, 32 pts/thread.
// ---------------------------------------------------------------------------
__global__ __launch_bounds__(128) void fps_kernel(const float* __restrict__ xyzs,
                                                  float* __restrict__ out_xyz) {
    const int g = blockIdx.x;
    const int b = g >> 4, f = g & 15;
    const float* fr = xyzs + ((size_t)(b * TFRAMES + 2 * f) * NPTS) * 3;
    const int tid = threadIdx.x;
    const int wid = tid >> 5, lane = tid & 31;

    __shared__ float sp[NPTS * 3];
    __shared__ ull wkey[2][4];
    for (int i = tid; i < NPTS * 3; i += 128) sp[i] = fr[i];
    __syncthreads();

    const ull ONE2 = packf(1.0f, 1.0f);
    ull px2[16], py2[16], pz2[16];
    float dist[32];
#pragma unroll
    for (int j = 0; j < 16; ++j) {
        int p0 = j * 256 + tid, p1 = p0 + 128;
        px2[j] = packf(sp[p0 * 3 + 0], sp[p1 * 3 + 0]);
        py2[j] = packf(sp[p0 * 3 + 1], sp[p1 * 3 + 1]);
        pz2[j] = packf(sp[p0 * 3 + 2], sp[p1 * 3 + 2]);
        dist[2 * j] = 1e10f; dist[2 * j + 1] = 1e10f;
    }

    float cx = sp[0], cy = sp[1], cz = sp[2];
    if (tid == 0) {
        float* o = out_xyz + (size_t)g * MANCH * 3;
        o[0] = cx; o[1] = cy; o[2] = cz;
    }

    for (int s = 1; s < MANCH; ++s) {
        const ull ncx2 = packf(-cx, -cx);
        const ull ncy2 = packf(-cy, -cy);
        const ull ncz2 = packf(-cz, -cz);
#pragma unroll
        for (int j = 0; j < 16; ++j) {
            ull ax = fma2(px2[j], ONE2, ncx2);
            ull ay = fma2(py2[j], ONE2, ncy2);
            ull az = fma2(pz2[j], ONE2, ncz2);
            ull mx = fma2(ax, ax, 0ull);
            ull my = fma2(ay, ay, 0ull);
            ull s1 = fma2(mx, ONE2, my);
            ull mz = fma2(az, az, 0ull);
            ull d2 = fma2(s1, ONE2, mz);
            float dlo, dhi;
            unpackf(d2, dlo, dhi);
            dist[2 * j]     = fminf(dist[2 * j], dlo);
            dist[2 * j + 1] = fminf(dist[2 * j + 1], dhi);
        }
        float t[16];
#pragma unroll
        for (int i = 0; i < 16; ++i) t[i] = fmaxf(dist[2 * i], dist[2 * i + 1]);
#pragma unroll
        for (int st = 8; st; st >>= 1)
#pragma unroll
            for (int i = 0; i < 8; ++i)
                if (i < st) t[i] = fmaxf(t[i], t[i + st]);
        unsigned wmax = __reduce_max_sync(0xffffffffu, __float_as_uint(t[0]));
        float wvf = __uint_as_float(wmax);
        unsigned cand = 0xffffffffu;
#pragma unroll
        for (int sl = 0; sl < 32; ++sl) {
            unsigned gi = (sl >> 1) * 256 + (sl & 1) * 128 + tid;
            if (dist[sl] == wvf) cand = min(cand, gi);
        }
        cand = __reduce_min_sync(0xffffffffu, cand);
        if (lane == 0)
            wkey[s & 1][wid] = ((ull)wmax << 32) | (unsigned)(~cand);
        __syncthreads();
        const ull* kk = wkey[s & 1];
        ull best = max(max(kk[0], kk[1]), max(kk[2], kk[3]));
        int wi = (int)(~(unsigned)best);
        cx = sp[wi * 3 + 0]; cy = sp[wi * 3 + 1]; cz = sp[wi * 3 + 2];
        if (tid == 0) {
            float* o = out_xyz + ((size_t)g * MANCH + s) * 3;
            o[0] = cx; o[1] = cy; o[2] = cz;
        }
    }
}

// ---------------------------------------------------------------------------
// Kernel 2: ball query (unchanged; proven)
// ---------------------------------------------------------------------------
__global__ __launch_bounds__(256) void ball_kernel(const float* __restrict__ xyzs,
                                                   const float* __restrict__ anchors) {
    const int bid = blockIdx.x;
    const int g = bid / 3, dti = bid % 3;
    const int dt = dti - 1;
    const int b = g >> 4, f = g & 15;
    int t = 2 * f + dt;
    t = min(max(t, 0), TFRAMES - 1);
    const float* fr = xyzs + (size_t)(b * TFRAMES + t) * NPTS * 3;

    __shared__ float sx[NPTS], sy[NPTS], sz[NPTS];
    for (int p = threadIdx.x; p < NPTS; p += 256) {
        const float* pp = fr + p * 3;
        sx[p] = pp[0]; sy[p] = pp[1]; sz[p] = pp[2];
    }
    __syncthreads();

    const int w = threadIdx.x >> 5;
    const int lane = threadIdx.x & 31;
    const float r2 = (float)(0.15 * 0.15);
    const float tch = (float)dt;
    const ull ONE2 = packf(1.0f, 1.0f);
    const unsigned below = (1u << lane) - 1u;

    for (int m = w; m < MANCH; m += 8) {
        const float* a = anchors + ((size_t)g * MANCH + m) * 3;
        const float ax = a[0], ay = a[1], az = a[2];
        const ull nax2 = packf(-ax, -ax);
        const ull nay2 = packf(-ay, -ay);
        const ull naz2 = packf(-az, -az);
        float4* od = g_disp + ((size_t)(dti * GROUPS + g) * MANCH + m) * KNBR;

        int filled = 0;
        int firstidx = -1;

        for (int base = 0; base < NPTS; base += 128) {
            const int j0 = base + 4 * lane;
            float4 X = *(const float4*)(sx + j0);
            float4 Y = *(const float4*)(sy + j0);
            float4 Z = *(const float4*)(sz + j0);
            ull dxa = fma2(packf(X.x, X.y), ONE2, nax2);
            ull dxb = fma2(packf(X.z, X.w), ONE2, nax2);
            ull dya = fma2(packf(Y.x, Y.y), ONE2, nay2);
            ull dyb = fma2(packf(Y.z, Y.w), ONE2, nay2);
            ull dza = fma2(packf(Z.x, Z.y), ONE2, naz2);
            ull dzb = fma2(packf(Z.z, Z.w), ONE2, naz2);
            ull s1a = fma2(fma2(dxa, dxa, 0ull), ONE2, fma2(dya, dya, 0ull));
            ull s1b = fma2(fma2(dxb, dxb, 0ull), ONE2, fma2(dyb, dyb, 0ull));
            ull d2a = fma2(s1a, ONE2, fma2(dza, dza, 0ull));
            ull d2b = fma2(s1b, ONE2, fma2(dzb, dzb, 0ull));
            float d0, d1, d2, d3;
            unpackf(d2a, d0, d1);
            unpackf(d2b, d2, d3);
            bool p0 = d0 < r2, p1 = d1 < r2, p2 = d2 < r2, p3 = d3 < r2;
            unsigned m0 = __ballot_sync(0xffffffffu, p0);
            unsigned m1 = __ballot_sync(0xffffffffu, p1);
            unsigned m2 = __ballot_sync(0xffffffffu, p2);
            unsigned m3 = __ballot_sync(0xffffffffu, p3);
            unsigned anyh = m0 | m1 | m2 | m3;
            if (anyh) {
                int pos = filled + __popc(m0 & below) + __popc(m1 & below)
                                 + __popc(m2 & below) + __popc(m3 & below);
                float x0, x1, y0, y1, z0, z1, x2, x3, y2, y3, z2, z3;
                unpackf(dxa, x0, x1); unpackf(dya, y0, y1); unpackf(dza, z0, z1);
                unpackf(dxb, x2, x3); unpackf(dyb, y2, y3); unpackf(dzb, z2, z3);
                if (p0) { if (pos < KNBR) od[pos] = make_float4(x0, y0, z0, tch); pos++; }
                if (p1) { if (pos < KNBR) od[pos] = make_float4(x1, y1, z1, tch); pos++; }
                if (p2) { if (pos < KNBR) od[pos] = make_float4(x2, y2, z2, tch); pos++; }
                if (p3) { if (pos < KNBR) od[pos] = make_float4(x3, y3, z3, tch); pos++; }
                if (firstidx < 0) {
                    unsigned i0 = m0 ? 4u * (__ffs(m0) - 1)     : 0xffffu;
                    unsigned i1 = m1 ? 4u * (__ffs(m1) - 1) + 1 : 0xffffu;
                    unsigned i2 = m2 ? 4u * (__ffs(m2) - 1) + 2 : 0xffffu;
                    unsigned i3 = m3 ? 4u * (__ffs(m3) - 1) + 3 : 0xffffu;
                    firstidx = base + (int)min(min(i0, i1), min(i2, i3));
                }
                filled += __popc(m0) + __popc(m1) + __popc(m2) + __popc(m3);
                if (filled >= KNBR) break;
            }
        }
        if (filled < KNBR) {
            int fi = (firstidx < 0) ? 0 : firstidx;
            float fx = sx[fi] - ax, fy = sy[fi] - ay, fz = sz[fi] - az;
            int s = filled + lane;
            if (s < KNBR) od[s] = make_float4(fx, fy, fz, tch);
        }
    }
}

// ---------------------------------------------------------------------------
// Kernel 3: MLP (R13 single-pass fp16), occupancy 3 blocks/SM for latency
// hiding (was 2).
// ---------------------------------------------------------------------------
#define HBW 36
#define TILEW (64 * HBW)
#define TILEB (TILEW * 4)

#define MMA_F16(d, a, b0, b1)                                                   \
    asm("mma.sync.aligned.m16n8k16.row.col.f32.f16.f16.f32 "                    \
        "{%0,%1,%2,%3}, {%4,%5,%6,%7}, {%8,%9}, {%0,%1,%2,%3};"                 \
        : "+f"((d)[0]), "+f"((d)[1]), "+f"((d)[2]), "+f"((d)[3])                \
        : "r"((a)[0]), "r"((a)[1]), "r"((a)[2]), "r"((a)[3]), "r"(b0), "r"(b1))

#define LDM_X4(r0, r1, r2, r3, addr)                                            \
    asm volatile("ldmatrix.sync.aligned.m8n8.x4.shared.b16 {%0,%1,%2,%3}, [%4];" \
        : "=r"(r0), "=r"(r1), "=r"(r2), "=r"(r3) : "r"(addr))

__global__ __launch_bounds__(128, 3) void mlp_kernel(const float* __restrict__ Wd,
                                                     const float* __restrict__ Wm,
                                                     float* __restrict__ out) {
    extern __shared__ __align__(16) uint32_t s_hb[];        // [2][3][TILEW]
    __shared__ __align__(16) ull s_wdp[2][16][4];
    __shared__ float s_obuf[C1 * 16];

    const int tid = threadIdx.x;
    const int w = tid >> 5, lane = tid & 31;
    const int q = lane & 3, nl = lane >> 2;
    const int g = blockIdx.x >> 3;
    const int m_base = (blockIdx.x & 7) * 16;

    {
        const int h = tid >> 6, j = (tid >> 2) & 15, c = tid & 3;
        const int c0 = 32 * h + 2 * j;
        s_wdp[h][j][c] = packf(Wd[c0 * 4 + c], Wd[(c0 + 1) * 4 + c]);
    }

    uint32_t Ah[2][4][4];
#pragma unroll
    for (int rr = 0; rr < 4; ++rr) {
        const int r = 32 * w + 16 * (rr >> 1) + 8 * (rr & 1) + nl;
        const float* wr = Wm + (size_t)r * C0;
#pragma unroll
        for (int kt = 0; kt < 4; ++kt)
#pragma unroll
            for (int hf = 0; hf < 2; ++hf) {
                float2 v = *(const float2*)(wr + kt * 16 + 8 * hf + 2 * q);
                __half2 h2 = __floats2half2_rn(v.x, v.y);
                Ah[rr >> 1][kt][(rr & 1) + 2 * hf] = *(uint32_t*)&h2;
            }
    }
    __syncthreads();

    const int l1_a  = tid >> 6;
    const int l1_k  = (tid >> 1) & 31;
    const int l1_ch = tid & 1;
    const int prow  = l1_a * 32 + l1_k;
    const ull* wp = &s_wdp[l1_ch][0][0];

    const uint32_t hb0 = (uint32_t)__cvta_generic_to_shared(&s_hb[0]);
    const uint32_t laneoff = (uint32_t)((lane & 7) * (HBW * 4) + (lane >> 3) * 16);

    auto produce = [&](int pair, int buf) {
        const int m = m_base + pair * 2 + l1_a;
        float4 dv[3];
#pragma unroll
        for (int sub = 0; sub < 3; ++sub)
            dv[sub] = g_disp[((size_t)(sub * GROUPS + g) * MANCH + m) * KNBR + l1_k];
#pragma unroll
        for (int sub = 0; sub < 3; ++sub) {
            const ull dvx2 = packf(dv[sub].x, dv[sub].x);
            const ull dvy2 = packf(dv[sub].y, dv[sub].y);
            const ull dvz2 = packf(dv[sub].z, dv[sub].z);
            const ull dvw2 = packf(dv[sub].w, dv[sub].w);
            uint32_t* hrow = &s_hb[(buf * 3 + sub) * TILEW + prow * HBW + l1_ch * 16];
#pragma unroll
            for (int j = 0; j < 16; ++j) {
                ull acc = fma2(wp[4 * j + 0], dvx2, 0ull);
                acc = fma2(wp[4 * j + 1], dvy2, acc);
                acc = fma2(wp[4 * j + 2], dvz2, acc);
                acc = fma2(wp[4 * j + 3], dvw2, acc);
                float h0, h1;
                unpackf(acc, h0, h1);
                __half2 p = __floats2half2_rn(fmaxf(h0, 0.f), fmaxf(h1, 0.f));
                hrow[j] = *(uint32_t*)&p;
            }
        }
    };

    float fsum[2][2][2];
#pragma unroll
    for (int i = 0; i < 8; ++i) (&fsum[0][0][0])[i] = 0.f;

    produce(0, 0);
    __syncthreads();

    for (int pair = 0; pair < 8; ++pair) {
        const int buf = pair & 1;
#pragma unroll
        for (int sub = 0; sub < 3; ++sub) {
            float acc[2][8][4];
#pragma unroll
            for (int i = 0; i < 64; ++i) (&acc[0][0][0])[i] = 0.f;
            const uint32_t ab = hb0 + (uint32_t)(buf * 3 + sub) * TILEB + laneoff;
#pragma unroll
            for (int ntp = 0; ntp < 4; ++ntp) {
                const int nt0 = 2 * ntp, nt1 = nt0 + 1;
                uint32_t b0[8], b1[8];
                const uint32_t r0 = (uint32_t)(nt0 * 8 * HBW * 4);
                const uint32_t r1 = (uint32_t)(nt1 * 8 * HBW * 4);
                LDM_X4(b0[0], b0[1], b0[2], b0[3], ab + r0);
                LDM_X4(b0[4], b0[5], b0[6], b0[7], ab + r0 + 64);
                LDM_X4(b1[0], b1[1], b1[2], b1[3], ab + r1);
                LDM_X4(b1[4], b1[5], b1[6], b1[7], ab + r1 + 64);
#pragma unroll
                for (int kt = 0; kt < 4; ++kt) {
#pragma unroll
                    for (int mt = 0; mt < 2; ++mt) {
                        MMA_F16(acc[mt][nt0], Ah[mt][kt], b0[2 * kt], b0[2 * kt + 1]);
                        MMA_F16(acc[mt][nt1], Ah[mt][kt], b1[2 * kt], b1[2 * kt + 1]);
                    }
                }
            }
#pragma unroll
            for (int mt = 0; mt < 2; ++mt)
#pragma unroll
                for (int a = 0; a < 2; ++a) {
                    float m0 = -1e30f, m1 = -1e30f;
#pragma unroll
                    for (int nt = a * 4; nt < a * 4 + 4; ++nt) {
                        m0 = fmaxf(m0, fmaxf(acc[mt][nt][0], acc[mt][nt][1]));
                        m1 = fmaxf(m1, fmaxf(acc[mt][nt][2], acc[mt][nt][3]));
                    }
                    m0 = fmaxf(m0, __shfl_xor_sync(0xffffffffu, m0, 1));
                    m0 = fmaxf(m0, __shfl_xor_sync(0xffffffffu, m0, 2));
                    m1 = fmaxf(m1, __shfl_xor_sync(0xffffffffu, m1, 1));
                    m1 = fmaxf(m1, __shfl_xor_sync(0xffffffffu, m1, 2));
                    fsum[mt][0][a] += fmaxf(m0, 0.f);
                    fsum[mt][1][a] += fmaxf(m1, 0.f);
                }
        }
        if (pair < 7) produce(pair + 1, buf ^ 1);
        if (q == 0) {
#pragma unroll
            for (int mt = 0; mt < 2; ++mt)
#pragma unroll
                for (int rh = 0; rh < 2; ++rh)
#pragma unroll
                    for (int a = 0; a < 2; ++a) {
                        int o = 32 * w + 16 * mt + 8 * rh + nl;
                        s_obuf[o * 16 + pair * 2 + a] = fsum[mt][rh][a];
                    }
        }
#pragma unroll
        for (int i = 0; i < 8; ++i) (&fsum[0][0][0])[i] = 0.f;
        __syncthreads();
    }

    float4* dst = (float4*)(out + 24576 + ((size_t)g * C1 + tid) * MANCH + m_base);
    const float4* src = (const float4*)(s_obuf + tid * 16);
#pragma unroll
    for (int i = 0; i < 4; ++i) dst[i] = src[i];
}

// ---------------------------------------------------------------------------
extern "C" void kernel_launch(void* const* d_in, const int* in_sizes, int n_in,
                              void* d_out, int out_size) {
    const float* xyzs = (const float*)d_in[0];
    const float* Wd   = (const float*)d_in[1];
    const float* Wm   = (const float*)d_in[2];
    float* out = (float*)d_out;

    cudaFuncSetAttribute(mlp_kernel, cudaFuncAttributeMaxDynamicSharedMemorySize,
                         2 * 3 * TILEB);

    fps_kernel<<<GROUPS, 128>>>(xyzs, out);
    ball_kernel<<<GROUPS * 3, 256>>>(xyzs, out);
    mlp_kernel<<<GROUPS * 8, 128, 2 * 3 * TILEB>>>(Wd, Wm, out);
}